// round 3
// baseline (speedup 1.0000x reference)
#include <cuda_runtime.h>
#include <cuda_bf16.h>
#include <math.h>

#define NN 100000
#define EE 1600000
#define BB 64
#define DIN 9
#define HD 128
#define LN_EPS 1e-5f

// ---------------- scratch (static device allocations only) ----------------
__device__ float g_h0[NN * HD];
__device__ float g_h1[NN * HD];
__device__ float g_agg[NN * HD];
__device__ int   g_deg[NN];
__device__ int   g_ptr[NN + 1];
__device__ int   g_cursor[NN];
__device__ int   g_csr[EE];
__device__ float g_psum[BB * HD];
__device__ unsigned g_pmax[BB * HD];
__device__ int   g_pcnt[BB];

// ---------------- init / zero ----------------
__global__ void init_kernel() {
    int i = blockIdx.x * blockDim.x + threadIdx.x;
    if (i < NN) g_deg[i] = 0;
    if (i < BB * HD) { g_psum[i] = 0.0f; g_pmax[i] = 0u; }
    if (i < BB) g_pcnt[i] = 0;
}

// ---------------- degree count ----------------
__global__ void deg_kernel(const int* __restrict__ dst) {
    int e = blockIdx.x * blockDim.x + threadIdx.x;
    if (e < EE) atomicAdd(&g_deg[dst[e]], 1);
}

// ---------------- single-block exclusive scan -> csr_ptr + cursor ----------------
__global__ void scan_kernel() {
    __shared__ int sh[1024];
    int tid = threadIdx.x;
    const int CH = (NN + 1023) / 1024;
    int base = tid * CH;
    int sum = 0;
    for (int i = 0; i < CH; i++) {
        int idx = base + i;
        if (idx < NN) sum += g_deg[idx];
    }
    sh[tid] = sum;
    __syncthreads();
    // Hillis-Steele inclusive scan over 1024 thread totals
    for (int off = 1; off < 1024; off <<= 1) {
        int v = (tid >= off) ? sh[tid - off] : 0;
        __syncthreads();
        sh[tid] += v;
        __syncthreads();
    }
    int run = (tid > 0) ? sh[tid - 1] : 0;
    for (int i = 0; i < CH; i++) {
        int idx = base + i;
        if (idx < NN) {
            g_ptr[idx] = run;
            g_cursor[idx] = run;
            run += g_deg[idx];
        }
    }
    if (tid == 1023) g_ptr[NN] = sh[1023];
}

// ---------------- CSR scatter ----------------
__global__ void build_csr_kernel(const int* __restrict__ src, const int* __restrict__ dst) {
    int e = blockIdx.x * blockDim.x + threadIdx.x;
    if (e < EE) {
        int pos = atomicAdd(&g_cursor[dst[e]], 1);
        g_csr[pos] = src[e];
    }
}

// ---------------- node embedder: Linear(9->128) + LN + ReLU ----------------
// 128 threads/block, ROWS_E rows per block
#define ROWS_E 16
__global__ void embed_kernel(const float* __restrict__ x,
                             const float* __restrict__ W0,
                             const float* __restrict__ b0,
                             const float* __restrict__ g0,
                             const float* __restrict__ be0,
                             float* __restrict__ hout) {
    __shared__ float sx[DIN];
    __shared__ float red[8];
    int tid = threadIdx.x;
    float gc = g0[tid], bec = be0[tid], bc = b0[tid];
    float w[DIN];
#pragma unroll
    for (int k = 0; k < DIN; k++) w[k] = W0[tid * DIN + k];

    int row0 = blockIdx.x * ROWS_E;
    for (int r = 0; r < ROWS_E; r++) {
        int row = row0 + r;
        if (tid < DIN) sx[tid] = x[row * DIN + tid];
        __syncthreads();
        float acc = bc;
#pragma unroll
        for (int k = 0; k < DIN; k++) acc += w[k] * sx[k];
        // LN over 128 lanes
        float s1 = acc, s2 = acc * acc;
#pragma unroll
        for (int o = 16; o; o >>= 1) {
            s1 += __shfl_xor_sync(0xffffffffu, s1, o);
            s2 += __shfl_xor_sync(0xffffffffu, s2, o);
        }
        int wi = tid >> 5, l = tid & 31;
        if (l == 0) { red[wi] = s1; red[wi + 4] = s2; }
        __syncthreads();
        float t1 = red[0] + red[1] + red[2] + red[3];
        float t2 = red[4] + red[5] + red[6] + red[7];
        float mean = t1 * (1.0f / HD);
        float var = t2 * (1.0f / HD) - mean * mean;
        float rs = rsqrtf(var + LN_EPS);
        float v = (acc - mean) * rs * gc + bec;
        hout[row * HD + tid] = fmaxf(v, 0.0f);
        __syncthreads();
    }
}

// ---------------- mean aggregation: warp per dst node, CSR gather ----------------
__global__ void aggregate_kernel(const float* __restrict__ hin) {
    int warp = (blockIdx.x * blockDim.x + threadIdx.x) >> 5;
    int lane = threadIdx.x & 31;
    if (warp >= NN) return;
    int s = g_ptr[warp], e = g_ptr[warp + 1];
    float a0 = 0.f, a1 = 0.f, a2 = 0.f, a3 = 0.f;
    for (int i = s; i < e; i++) {
        int src = __ldg(&g_csr[i]);
        float4 v = *reinterpret_cast<const float4*>(hin + (size_t)src * HD + lane * 4);
        a0 += v.x; a1 += v.y; a2 += v.z; a3 += v.w;
    }
    int deg = e - s;
    float inv = 1.0f / (float)max(deg, 1);
    float4 out;
    out.x = a0 * inv; out.y = a1 * inv; out.z = a2 * inv; out.w = a3 * inv;
    *reinterpret_cast<float4*>(g_agg + (size_t)warp * HD + lane * 4) = out;
}

// ---------------- SAGE: lin_l(agg)+bl + lin_r(h)  -> LN -> ReLU ----------------
// 128 threads/block (thread = out channel), ROWS_G rows per block
#define ROWS_G 16
__global__ void sage_kernel(const float* __restrict__ hin,
                            const float* __restrict__ Wl,
                            const float* __restrict__ bl,
                            const float* __restrict__ Wr,
                            const float* __restrict__ gg,
                            const float* __restrict__ be,
                            float* __restrict__ hout) {
    __shared__ float sa[HD];
    __shared__ float shh[HD];
    __shared__ float red[8];
    int tid = threadIdx.x;
    float gc = gg[tid], bec = be[tid], blc = bl[tid];
    const float4* wl4 = reinterpret_cast<const float4*>(Wl + tid * HD);
    const float4* wr4 = reinterpret_cast<const float4*>(Wr + tid * HD);

    int row0 = blockIdx.x * ROWS_G;
    for (int r = 0; r < ROWS_G; r++) {
        int row = row0 + r;
        sa[tid]  = g_agg[(size_t)row * HD + tid];
        shh[tid] = hin[(size_t)row * HD + tid];
        __syncthreads();
        const float4* xa = reinterpret_cast<const float4*>(sa);
        const float4* xh = reinterpret_cast<const float4*>(shh);
        float a0 = 0.f, a1 = 0.f, a2 = 0.f, a3 = 0.f;
#pragma unroll
        for (int k = 0; k < HD / 4; k++) {
            float4 w = wl4[k];
            float4 xv = xa[k];
            a0 += w.x * xv.x; a1 += w.y * xv.y; a2 += w.z * xv.z; a3 += w.w * xv.w;
            float4 w2 = wr4[k];
            float4 x2 = xh[k];
            a0 += w2.x * x2.x; a1 += w2.y * x2.y; a2 += w2.z * x2.z; a3 += w2.w * x2.w;
        }
        float acc = blc + ((a0 + a1) + (a2 + a3));
        // LN over 128 lanes
        float s1 = acc, s2 = acc * acc;
#pragma unroll
        for (int o = 16; o; o >>= 1) {
            s1 += __shfl_xor_sync(0xffffffffu, s1, o);
            s2 += __shfl_xor_sync(0xffffffffu, s2, o);
        }
        int wi = tid >> 5, l = tid & 31;
        if (l == 0) { red[wi] = s1; red[wi + 4] = s2; }
        __syncthreads();
        float t1 = red[0] + red[1] + red[2] + red[3];
        float t2 = red[4] + red[5] + red[6] + red[7];
        float mean = t1 * (1.0f / HD);
        float var = t2 * (1.0f / HD) - mean * mean;
        float rs = rsqrtf(var + LN_EPS);
        float v = (acc - mean) * rs * gc + bec;
        hout[(size_t)row * HD + tid] = fmaxf(v, 0.0f);
        __syncthreads();
    }
}

// ---------------- pooling: per-block running sum/max over sorted batch ----------------
#define POOL_CHUNK 256
__global__ void pool_kernel(const float* __restrict__ node,
                            const int* __restrict__ batch) {
    int n0 = blockIdx.x * POOL_CHUNK;
    int n1 = min(n0 + POOL_CHUNK, NN);
    int c = threadIdx.x;
    int cur = __ldg(&batch[n0]);
    float s = 0.0f, m = 0.0f;
    int cnt = 0;
    for (int i = n0; i < n1; i++) {
        int b = __ldg(&batch[i]);
        if (b != cur) {
            atomicAdd(&g_psum[cur * HD + c], s);
            atomicMax(&g_pmax[cur * HD + c], __float_as_uint(m));
            if (c == 0) atomicAdd(&g_pcnt[cur], cnt);
            cur = b; s = 0.0f; m = 0.0f; cnt = 0;
        }
        float v = node[(size_t)i * HD + c];
        s += v;
        m = fmaxf(m, v);
        cnt++;
    }
    atomicAdd(&g_psum[cur * HD + c], s);
    atomicMax(&g_pmax[cur * HD + c], __float_as_uint(m));
    if (c == 0) atomicAdd(&g_pcnt[cur], cnt);
}

__global__ void finalize_kernel(float* __restrict__ out) {
    int i = blockIdx.x * blockDim.x + threadIdx.x; // B*H
    if (i >= BB * HD) return;
    int b = i >> 7;
    int c = i & (HD - 1);
    float cnt = fmaxf((float)g_pcnt[b], 1.0f);
    out[(size_t)NN * HD + b * (2 * HD) + c] = g_psum[i] / cnt;
    out[(size_t)NN * HD + b * (2 * HD) + HD + c] = __uint_as_float(g_pmax[i]);
}

// ---------------- launch ----------------
extern "C" void kernel_launch(void* const* d_in, const int* in_sizes, int n_in,
                              void* d_out, int out_size) {
    const float* x   = (const float*)d_in[0];
    const int* eidx  = (const int*)d_in[1];
    const int* batch = (const int*)d_in[2];
    const float* W0 = (const float*)d_in[3];
    const float* b0 = (const float*)d_in[4];
    const float* g0 = (const float*)d_in[5];
    const float* be0 = (const float*)d_in[6];
    const float* Wl1 = (const float*)d_in[7];
    const float* bl1 = (const float*)d_in[8];
    const float* Wr1 = (const float*)d_in[9];
    const float* g1 = (const float*)d_in[10];
    const float* be1 = (const float*)d_in[11];
    const float* Wl2 = (const float*)d_in[12];
    const float* bl2 = (const float*)d_in[13];
    const float* Wr2 = (const float*)d_in[14];
    const float* g2 = (const float*)d_in[15];
    const float* be2 = (const float*)d_in[16];
    const float* Wl3 = (const float*)d_in[17];
    const float* bl3 = (const float*)d_in[18];
    const float* Wr3 = (const float*)d_in[19];
    const float* g3 = (const float*)d_in[20];
    const float* be3 = (const float*)d_in[21];
    float* out = (float*)d_out;

    const int* src = eidx;       // edge_index[0]
    const int* dst = eidx + EE;  // edge_index[1]

    // init + CSR build
    init_kernel<<<(NN + 255) / 256, 256>>>();
    deg_kernel<<<(EE + 255) / 256, 256>>>(dst);
    scan_kernel<<<1, 1024>>>();
    build_csr_kernel<<<(EE + 255) / 256, 256>>>(src, dst);

    // embed
    embed_kernel<<<NN / ROWS_E, HD>>>(x, W0, b0, g0, be0, g_h0);

    int agg_blocks = (NN * 32 + 255) / 256;

    // layer 1: h0 -> h1
    aggregate_kernel<<<agg_blocks, 256>>>(g_h0);
    sage_kernel<<<NN / ROWS_G, HD>>>(g_h0, Wl1, bl1, Wr1, g1, be1, g_h1);
    // layer 2: h1 -> h0
    aggregate_kernel<<<agg_blocks, 256>>>(g_h1);
    sage_kernel<<<NN / ROWS_G, HD>>>(g_h1, Wl2, bl2, Wr2, g2, be2, g_h0);
    // layer 3: h0 -> d_out (node_embed section)
    aggregate_kernel<<<agg_blocks, 256>>>(g_h0);
    sage_kernel<<<NN / ROWS_G, HD>>>(g_h0, Wl3, bl3, Wr3, g3, be3, out);

    // pooling
    pool_kernel<<<(NN + POOL_CHUNK - 1) / POOL_CHUNK, HD>>>(out, batch);
    finalize_kernel<<<(BB * HD + 255) / 256, 256>>>(out);
}

// round 5
// speedup vs baseline: 1.4685x; 1.4685x over previous
#include <cuda_runtime.h>
#include <cuda_bf16.h>
#include <math.h>

#define NN 100000
#define EE 1600000
#define BB 64
#define DIN 9
#define HD 128
#define LN_EPS 1e-5f

// ---------------- scratch (static device allocations only) ----------------
__device__ float g_h0[NN * HD];
__device__ float g_h1[NN * HD];
__device__ float g_agg[NN * HD];
__device__ int   g_deg[NN];
__device__ int   g_ptr[NN + 1];
__device__ int   g_cursor[NN];
__device__ int   g_csr[EE];
__device__ float g_psum[BB * HD];
__device__ unsigned g_pmax[BB * HD];
__device__ int   g_pcnt[BB];

// ---------------- init / zero ----------------
__global__ void init_kernel() {
    int i = blockIdx.x * blockDim.x + threadIdx.x;
    if (i < NN) g_deg[i] = 0;
    if (i < BB * HD) { g_psum[i] = 0.0f; g_pmax[i] = 0u; }
    if (i < BB) g_pcnt[i] = 0;
}

// ---------------- degree count ----------------
__global__ void deg_kernel(const int* __restrict__ dst) {
    int e = blockIdx.x * blockDim.x + threadIdx.x;
    if (e < EE) atomicAdd(&g_deg[dst[e]], 1);
}

// ---------------- single-block exclusive scan -> csr_ptr + cursor ----------------
__global__ void scan_kernel() {
    __shared__ int sh[1024];
    int tid = threadIdx.x;
    const int CH = (NN + 1023) / 1024;
    int base = tid * CH;
    int sum = 0;
    for (int i = 0; i < CH; i++) {
        int idx = base + i;
        if (idx < NN) sum += g_deg[idx];
    }
    sh[tid] = sum;
    __syncthreads();
    for (int off = 1; off < 1024; off <<= 1) {
        int v = (tid >= off) ? sh[tid - off] : 0;
        __syncthreads();
        sh[tid] += v;
        __syncthreads();
    }
    int run = (tid > 0) ? sh[tid - 1] : 0;
    for (int i = 0; i < CH; i++) {
        int idx = base + i;
        if (idx < NN) {
            g_ptr[idx] = run;
            g_cursor[idx] = run;
            run += g_deg[idx];
        }
    }
    if (tid == 1023) g_ptr[NN] = sh[1023];
}

// ---------------- CSR scatter ----------------
__global__ void build_csr_kernel(const int* __restrict__ src, const int* __restrict__ dst) {
    int e = blockIdx.x * blockDim.x + threadIdx.x;
    if (e < EE) {
        int pos = atomicAdd(&g_cursor[dst[e]], 1);
        g_csr[pos] = src[e];
    }
}

// ---------------- node embedder: Linear(9->128) + LN + ReLU ----------------
#define ROWS_E 16
__global__ void embed_kernel(const float* __restrict__ x,
                             const float* __restrict__ W0,
                             const float* __restrict__ b0,
                             const float* __restrict__ g0,
                             const float* __restrict__ be0,
                             float* __restrict__ hout) {
    __shared__ float sx[DIN];
    __shared__ float red[8];
    int tid = threadIdx.x;
    float gc = g0[tid], bec = be0[tid], bc = b0[tid];
    float w[DIN];
#pragma unroll
    for (int k = 0; k < DIN; k++) w[k] = W0[tid * DIN + k];

    int row0 = blockIdx.x * ROWS_E;
    for (int r = 0; r < ROWS_E; r++) {
        int row = row0 + r;
        if (tid < DIN) sx[tid] = x[row * DIN + tid];
        __syncthreads();
        float acc = bc;
#pragma unroll
        for (int k = 0; k < DIN; k++) acc += w[k] * sx[k];
        float s1 = acc, s2 = acc * acc;
#pragma unroll
        for (int o = 16; o; o >>= 1) {
            s1 += __shfl_xor_sync(0xffffffffu, s1, o);
            s2 += __shfl_xor_sync(0xffffffffu, s2, o);
        }
        int wi = tid >> 5, l = tid & 31;
        if (l == 0) { red[wi] = s1; red[wi + 4] = s2; }
        __syncthreads();
        float t1 = red[0] + red[1] + red[2] + red[3];
        float t2 = red[4] + red[5] + red[6] + red[7];
        float mean = t1 * (1.0f / HD);
        float var = t2 * (1.0f / HD) - mean * mean;
        float rs = rsqrtf(var + LN_EPS);
        float v = (acc - mean) * rs * gc + bec;
        hout[row * HD + tid] = fmaxf(v, 0.0f);
        __syncthreads();
    }
}

// ---------------- mean aggregation: warp per dst node, CSR gather ----------------
__global__ void aggregate_kernel(const float* __restrict__ hin) {
    int warp = (blockIdx.x * blockDim.x + threadIdx.x) >> 5;
    int lane = threadIdx.x & 31;
    if (warp >= NN) return;
    int s = g_ptr[warp], e = g_ptr[warp + 1];
    float a0 = 0.f, a1 = 0.f, a2 = 0.f, a3 = 0.f;
    for (int i = s; i < e; i++) {
        int src = __ldg(&g_csr[i]);
        float4 v = *reinterpret_cast<const float4*>(hin + (size_t)src * HD + lane * 4);
        a0 += v.x; a1 += v.y; a2 += v.z; a3 += v.w;
    }
    int deg = e - s;
    float inv = 1.0f / (float)max(deg, 1);
    float4 out;
    out.x = a0 * inv; out.y = a1 * inv; out.z = a2 * inv; out.w = a3 * inv;
    *reinterpret_cast<float4*>(g_agg + (size_t)warp * HD + lane * 4) = out;
}

// ---------------- SAGE as SMEM-resident GEMM + fused LN/ReLU ----------------
// Block: 256 threads = 2 row-slots x 128 channels. Weights (both matrices,
// 128KB) packed once per block into dynamic SMEM as [k4][c] float4 with XOR
// swizzle (c ^ k4) so packing STS and mainloop LDS are low-conflict.
// Each thread computes 1 channel for 8 rows (register tile), reusing each
// weight float4 8x -> FMA-issue-bound instead of L1-wavefront-bound.
#define SAGE_R 8
#define SAGE_RS 2
#define SAGE_RI (SAGE_R * SAGE_RS)   // 16 rows per iteration
#define SAGE_RPB 128                 // rows per block

#define W_IDX(k4, c) ((k4) * 128 + ((c) ^ (k4)))

// dynamic smem bytes: 2 * 32*128*16 (weights) + 2 * 16*128*4 (x) + 512 (red)
#define SAGE_SMEM (2 * 32 * 128 * 16 + 2 * SAGE_RI * HD * 4 + 512)

__global__ __launch_bounds__(256, 1)
void sage_gemm_kernel(const float* __restrict__ hin,
                      const float* __restrict__ Wl,
                      const float* __restrict__ bl,
                      const float* __restrict__ Wr,
                      const float* __restrict__ gg,
                      const float* __restrict__ be,
                      float* __restrict__ hout) {
    extern __shared__ float smem[];
    float4* wl_s = (float4*)smem;                 // [32][128] swizzled
    float4* wr_s = wl_s + 32 * 128;               // [32][128] swizzled
    float*  sxa  = (float*)(wr_s + 32 * 128);     // [16][128]
    float*  sxh  = sxa + SAGE_RI * HD;            // [16][128]
    float*  red  = sxh + SAGE_RI * HD;            // [16][4][2]

    int tid = threadIdx.x;
    int c   = tid & 127;          // channel
    int rs  = tid >> 7;           // row slot 0/1
    int lane = tid & 31;
    int wi  = (tid >> 5) & 3;     // warp within row group

    // pack weights: gmem read coalesced (consecutive k4 per lane),
    // SMEM store swizzled (~4-way conflict, one-time)
    for (int i = tid; i < 128 * 32; i += 256) {
        int cc = i >> 5;
        int k4 = i & 31;
        wl_s[W_IDX(k4, cc)] = ((const float4*)Wl)[cc * 32 + k4];
        wr_s[W_IDX(k4, cc)] = ((const float4*)Wr)[cc * 32 + k4];
    }

    float blc = bl[c], gc = gg[c], bec = be[c];
    __syncthreads();

    int row_base = blockIdx.x * SAGE_RPB;
    int row_end  = min(row_base + SAGE_RPB, NN);

    for (int r0 = row_base; r0 < row_end; r0 += SAGE_RI) {
        // stage 16 rows of agg and h
        for (int j = tid; j < SAGE_RI * HD; j += 256) {
            int row = r0 + (j >> 7);
            float va = 0.0f, vh = 0.0f;
            if (row < NN) {
                va = g_agg[(size_t)row * HD + (j & 127)];
                vh = hin[(size_t)row * HD + (j & 127)];
            }
            sxa[j] = va; sxh[j] = vh;
        }
        __syncthreads();

        float acc[SAGE_R];
#pragma unroll
        for (int r = 0; r < SAGE_R; r++) acc[r] = blc;

        const float4* xa4 = (const float4*)(sxa + (rs * SAGE_R) * HD);
        const float4* xh4 = (const float4*)(sxh + (rs * SAGE_R) * HD);

#pragma unroll 4
        for (int k4 = 0; k4 < 32; k4++) {
            float4 w1 = wl_s[W_IDX(k4, c)];
            float4 w2 = wr_s[W_IDX(k4, c)];
#pragma unroll
            for (int r = 0; r < SAGE_R; r++) {
                float4 xa = xa4[r * 32 + k4];   // broadcast within warp
                float4 xh = xh4[r * 32 + k4];
                acc[r] += w1.x * xa.x + w1.y * xa.y + w1.z * xa.z + w1.w * xa.w
                        + w2.x * xh.x + w2.y * xh.y + w2.z * xh.z + w2.w * xh.w;
            }
        }

        // fused LayerNorm + ReLU, one reduction per row over 128 channels
        float s1v[SAGE_R], s2v[SAGE_R];
#pragma unroll
        for (int r = 0; r < SAGE_R; r++) {
            float s1 = acc[r], s2 = acc[r] * acc[r];
#pragma unroll
            for (int o = 16; o; o >>= 1) {
                s1 += __shfl_xor_sync(0xffffffffu, s1, o);
                s2 += __shfl_xor_sync(0xffffffffu, s2, o);
            }
            s1v[r] = s1; s2v[r] = s2;
        }
        if (lane == 0) {
#pragma unroll
            for (int r = 0; r < SAGE_R; r++) {
                int rr = rs * SAGE_R + r;
                red[(rr * 4 + wi) * 2 + 0] = s1v[r];
                red[(rr * 4 + wi) * 2 + 1] = s2v[r];
            }
        }
        __syncthreads();
#pragma unroll
        for (int r = 0; r < SAGE_R; r++) {
            int rr = rs * SAGE_R + r;
            float t1 = red[(rr * 4 + 0) * 2] + red[(rr * 4 + 1) * 2]
                     + red[(rr * 4 + 2) * 2] + red[(rr * 4 + 3) * 2];
            float t2 = red[(rr * 4 + 0) * 2 + 1] + red[(rr * 4 + 1) * 2 + 1]
                     + red[(rr * 4 + 2) * 2 + 1] + red[(rr * 4 + 3) * 2 + 1];
            float mean = t1 * (1.0f / HD);
            float var  = t2 * (1.0f / HD) - mean * mean;
            float rsv  = rsqrtf(var + LN_EPS);
            float v = (acc[r] - mean) * rsv * gc + bec;
            int row = r0 + rr;
            if (row < NN) hout[(size_t)row * HD + c] = fmaxf(v, 0.0f);
        }
        __syncthreads();   // protect sxa/sxh + red reuse
    }
}

// ---------------- pooling: per-block running sum/max over sorted batch ----------------
#define POOL_CHUNK 256
__global__ void pool_kernel(const float* __restrict__ node,
                            const int* __restrict__ batch) {
    int n0 = blockIdx.x * POOL_CHUNK;
    int n1 = min(n0 + POOL_CHUNK, NN);
    int c = threadIdx.x;
    int cur = __ldg(&batch[n0]);
    float s = 0.0f, m = 0.0f;
    int cnt = 0;
    for (int i = n0; i < n1; i++) {
        int b = __ldg(&batch[i]);
        if (b != cur) {
            atomicAdd(&g_psum[cur * HD + c], s);
            atomicMax(&g_pmax[cur * HD + c], __float_as_uint(m));
            if (c == 0) atomicAdd(&g_pcnt[cur], cnt);
            cur = b; s = 0.0f; m = 0.0f; cnt = 0;
        }
        float v = node[(size_t)i * HD + c];
        s += v;
        m = fmaxf(m, v);
        cnt++;
    }
    atomicAdd(&g_psum[cur * HD + c], s);
    atomicMax(&g_pmax[cur * HD + c], __float_as_uint(m));
    if (c == 0) atomicAdd(&g_pcnt[cur], cnt);
}

__global__ void finalize_kernel(float* __restrict__ out) {
    int i = blockIdx.x * blockDim.x + threadIdx.x; // B*H
    if (i >= BB * HD) return;
    int b = i >> 7;
    int c = i & (HD - 1);
    float cnt = fmaxf((float)g_pcnt[b], 1.0f);
    out[(size_t)NN * HD + b * (2 * HD) + c] = g_psum[i] / cnt;
    out[(size_t)NN * HD + b * (2 * HD) + HD + c] = __uint_as_float(g_pmax[i]);
}

// ---------------- launch ----------------
extern "C" void kernel_launch(void* const* d_in, const int* in_sizes, int n_in,
                              void* d_out, int out_size) {
    const float* x   = (const float*)d_in[0];
    const int* eidx  = (const int*)d_in[1];
    const int* batch = (const int*)d_in[2];
    const float* W0 = (const float*)d_in[3];
    const float* b0 = (const float*)d_in[4];
    const float* g0 = (const float*)d_in[5];
    const float* be0 = (const float*)d_in[6];
    const float* Wl1 = (const float*)d_in[7];
    const float* bl1 = (const float*)d_in[8];
    const float* Wr1 = (const float*)d_in[9];
    const float* g1 = (const float*)d_in[10];
    const float* be1 = (const float*)d_in[11];
    const float* Wl2 = (const float*)d_in[12];
    const float* bl2 = (const float*)d_in[13];
    const float* Wr2 = (const float*)d_in[14];
    const float* g2 = (const float*)d_in[15];
    const float* be2 = (const float*)d_in[16];
    const float* Wl3 = (const float*)d_in[17];
    const float* bl3 = (const float*)d_in[18];
    const float* Wr3 = (const float*)d_in[19];
    const float* g3 = (const float*)d_in[20];
    const float* be3 = (const float*)d_in[21];
    float* out = (float*)d_out;

    const int* src = eidx;       // edge_index[0]
    const int* dst = eidx + EE;  // edge_index[1]

    static int smem_set = 0;
    if (!smem_set) {
        cudaFuncSetAttribute(sage_gemm_kernel,
                             cudaFuncAttributeMaxDynamicSharedMemorySize, SAGE_SMEM);
        smem_set = 1;
    }

    // init + CSR build
    init_kernel<<<(NN + 255) / 256, 256>>>();
    deg_kernel<<<(EE + 255) / 256, 256>>>(dst);
    scan_kernel<<<1, 1024>>>();
    build_csr_kernel<<<(EE + 255) / 256, 256>>>(src, dst);

    // embed
    embed_kernel<<<NN / ROWS_E, HD>>>(x, W0, b0, g0, be0, g_h0);

    int agg_blocks = (NN * 32 + 255) / 256;
    int sage_blocks = (NN + SAGE_RPB - 1) / SAGE_RPB;

    // layer 1: h0 -> h1
    aggregate_kernel<<<agg_blocks, 256>>>(g_h0);
    sage_gemm_kernel<<<sage_blocks, 256, SAGE_SMEM>>>(g_h0, Wl1, bl1, Wr1, g1, be1, g_h1);
    // layer 2: h1 -> h0
    aggregate_kernel<<<agg_blocks, 256>>>(g_h1);
    sage_gemm_kernel<<<sage_blocks, 256, SAGE_SMEM>>>(g_h1, Wl2, bl2, Wr2, g2, be2, g_h0);
    // layer 3: h0 -> d_out (node_embed section)
    aggregate_kernel<<<agg_blocks, 256>>>(g_h0);
    sage_gemm_kernel<<<sage_blocks, 256, SAGE_SMEM>>>(g_h0, Wl3, bl3, Wr3, g3, be3, out);

    // pooling
    pool_kernel<<<(NN + POOL_CHUNK - 1) / POOL_CHUNK, HD>>>(out, batch);
    finalize_kernel<<<(BB * HD + 255) / 256, 256>>>(out);
}

// round 8
// speedup vs baseline: 1.6252x; 1.1067x over previous
#include <cuda_runtime.h>
#include <math.h>

#define NN 100000
#define EE 1600000
#define BB 64
#define DIN 9
#define HD 128
#define KK 256
#define LN_EPS 1e-5f

// ---------------- scratch ----------------
__device__ float g_h0[NN * HD];
__device__ float g_h1[NN * HD];
__device__ float g_agg[NN * HD];
__device__ float g_wT[3 * KK * HD];   // per layer: [k][c]; k<128 = Wl^T, k>=128 = Wr^T
__device__ int   g_deg[NN];
__device__ int   g_ptr[NN + 1];
__device__ int   g_cursor[NN];
__device__ int   g_csr[EE];
__device__ float g_psum[BB * HD];
__device__ unsigned g_pmax[BB * HD];
__device__ int   g_pcnt[BB];

// ---------------- init ----------------
__global__ void init_kernel() {
    int i = blockIdx.x * blockDim.x + threadIdx.x;
    if (i < NN) g_deg[i] = 0;
    if (i < BB * HD) { g_psum[i] = 0.0f; g_pmax[i] = 0u; }
    if (i < BB) g_pcnt[i] = 0;
}

// ---------------- weight pre-transpose: g_wT[L][k][c] ----------------
__global__ void wt_kernel(const float* __restrict__ Wl1, const float* __restrict__ Wr1,
                          const float* __restrict__ Wl2, const float* __restrict__ Wr2,
                          const float* __restrict__ Wl3, const float* __restrict__ Wr3) {
    int i = blockIdx.x * blockDim.x + threadIdx.x;   // 3 * 256 * 128
    if (i >= 3 * KK * HD) return;
    int c = i & 127;
    int k = (i >> 7) & 255;
    int L = i >> 15;
    const float* W;
    int kk = k;
    if (k < HD) {
        W = (L == 0) ? Wl1 : (L == 1) ? Wl2 : Wl3;
    } else {
        W = (L == 0) ? Wr1 : (L == 1) ? Wr2 : Wr3;
        kk = k - HD;
    }
    g_wT[i] = W[c * HD + kk];
}

// ---------------- degree count ----------------
__global__ void deg_kernel(const int* __restrict__ dst) {
    int e = blockIdx.x * blockDim.x + threadIdx.x;
    if (e < EE) atomicAdd(&g_deg[dst[e]], 1);
}

// ---------------- single-block exclusive scan ----------------
__global__ void scan_kernel() {
    __shared__ int sh[1024];
    int tid = threadIdx.x;
    const int CH = (NN + 1023) / 1024;
    int base = tid * CH;
    int sum = 0;
    for (int i = 0; i < CH; i++) {
        int idx = base + i;
        if (idx < NN) sum += g_deg[idx];
    }
    sh[tid] = sum;
    __syncthreads();
    for (int off = 1; off < 1024; off <<= 1) {
        int v = (tid >= off) ? sh[tid - off] : 0;
        __syncthreads();
        sh[tid] += v;
        __syncthreads();
    }
    int run = (tid > 0) ? sh[tid - 1] : 0;
    for (int i = 0; i < CH; i++) {
        int idx = base + i;
        if (idx < NN) {
            g_ptr[idx] = run;
            g_cursor[idx] = run;
            run += g_deg[idx];
        }
    }
    if (tid == 1023) g_ptr[NN] = sh[1023];
}

// ---------------- CSR scatter ----------------
__global__ void build_csr_kernel(const int* __restrict__ src, const int* __restrict__ dst) {
    int e = blockIdx.x * blockDim.x + threadIdx.x;
    if (e < EE) {
        int pos = atomicAdd(&g_cursor[dst[e]], 1);
        g_csr[pos] = src[e];
    }
}

// ---------------- node embedder: Linear(9->128) + LN + ReLU ----------------
#define ROWS_E 16
__global__ void embed_kernel(const float* __restrict__ x,
                             const float* __restrict__ W0,
                             const float* __restrict__ b0,
                             const float* __restrict__ g0,
                             const float* __restrict__ be0,
                             float* __restrict__ hout) {
    __shared__ float sx[DIN];
    __shared__ float red[8];
    int tid = threadIdx.x;
    float gc = g0[tid], bec = be0[tid], bc = b0[tid];
    float w[DIN];
#pragma unroll
    for (int k = 0; k < DIN; k++) w[k] = W0[tid * DIN + k];

    int row0 = blockIdx.x * ROWS_E;
    for (int r = 0; r < ROWS_E; r++) {
        int row = row0 + r;
        if (tid < DIN) sx[tid] = x[row * DIN + tid];
        __syncthreads();
        float acc = bc;
#pragma unroll
        for (int k = 0; k < DIN; k++) acc += w[k] * sx[k];
        float s1 = acc, s2 = acc * acc;
#pragma unroll
        for (int o = 16; o; o >>= 1) {
            s1 += __shfl_xor_sync(0xffffffffu, s1, o);
            s2 += __shfl_xor_sync(0xffffffffu, s2, o);
        }
        int wi = tid >> 5, l = tid & 31;
        if (l == 0) { red[wi] = s1; red[wi + 4] = s2; }
        __syncthreads();
        float t1 = red[0] + red[1] + red[2] + red[3];
        float t2 = red[4] + red[5] + red[6] + red[7];
        float mean = t1 * (1.0f / HD);
        float var = t2 * (1.0f / HD) - mean * mean;
        float rs = rsqrtf(var + LN_EPS);
        float v = (acc - mean) * rs * gc + bec;
        hout[row * HD + tid] = fmaxf(v, 0.0f);
        __syncthreads();
    }
}

// ---------------- mean aggregation: warp per dst node, MLP-4 unrolled ----------------
__global__ void aggregate_kernel(const float* __restrict__ hin) {
    int warp = (blockIdx.x * blockDim.x + threadIdx.x) >> 5;
    int lane = threadIdx.x & 31;
    if (warp >= NN) return;
    int s = g_ptr[warp], e = g_ptr[warp + 1];
    float a0 = 0.f, a1 = 0.f, a2 = 0.f, a3 = 0.f;
    int i = s;
    for (; i + 4 <= e; i += 4) {
        int s0 = __ldg(&g_csr[i + 0]);
        int s1 = __ldg(&g_csr[i + 1]);
        int s2 = __ldg(&g_csr[i + 2]);
        int s3 = __ldg(&g_csr[i + 3]);
        float4 v0 = __ldg((const float4*)(hin + (size_t)s0 * HD) + lane);
        float4 v1 = __ldg((const float4*)(hin + (size_t)s1 * HD) + lane);
        float4 v2 = __ldg((const float4*)(hin + (size_t)s2 * HD) + lane);
        float4 v3 = __ldg((const float4*)(hin + (size_t)s3 * HD) + lane);
        a0 += (v0.x + v1.x) + (v2.x + v3.x);
        a1 += (v0.y + v1.y) + (v2.y + v3.y);
        a2 += (v0.z + v1.z) + (v2.z + v3.z);
        a3 += (v0.w + v1.w) + (v2.w + v3.w);
    }
    for (; i < e; i++) {
        int s0 = __ldg(&g_csr[i]);
        float4 v = __ldg((const float4*)(hin + (size_t)s0 * HD) + lane);
        a0 += v.x; a1 += v.y; a2 += v.z; a3 += v.w;
    }
    int deg = e - s;
    float inv = 1.0f / (float)max(deg, 1);
    float4 out;
    out.x = a0 * inv; out.y = a1 * inv; out.z = a2 * inv; out.w = a3 * inv;
    *reinterpret_cast<float4*>(g_agg + (size_t)warp * HD + lane * 4) = out;
}

// ---------------- SAGE: 128x128xK=256 register-tiled GEMM + fused LN/ReLU ----------------
// 256 threads: tx = tid&31 -> channels tx*4..+3; wy = tid>>5 -> rows wy*16..+15.
// K staged in 4 chunks of 64 (agg[0:64], agg[64:128], h[0:64], h[64:128]).
// Dynamic smem: w_s[64][128] + x_s[128][64] = 64KB -> 2 CTAs/SM.
#define SBK 64
#define SAGE2_SMEM (SBK * HD * 4 + 128 * SBK * 4)   // 65536

__global__ __launch_bounds__(256, 2)
void sage2_kernel(const float* __restrict__ hin,
                  const float* __restrict__ wT,
                  const float* __restrict__ bl,
                  const float* __restrict__ gg,
                  const float* __restrict__ be,
                  float* __restrict__ hout) {
    extern __shared__ float sm[];
    float* w_s = sm;                 // [64][128]
    float* x_s = sm + SBK * HD;      // [128][64]

    int tid = threadIdx.x;
    int tx = tid & 31;
    int wy = tid >> 5;
    int row0 = blockIdx.x * 128;

    float acc[16][4];
#pragma unroll
    for (int r = 0; r < 16; r++) {
        acc[r][0] = 0.f; acc[r][1] = 0.f; acc[r][2] = 0.f; acc[r][3] = 0.f;
    }

    for (int ch = 0; ch < 4; ch++) {
        const float* xsrc = (ch < 2) ? g_agg : hin;
        int kofs = (ch & 1) * SBK;
        // stage x: 128 rows x 64 k, coalesced LDG, conflict-free STS.128
        {
            int k4 = tid & 15, rr = tid >> 4;
#pragma unroll
            for (int it = 0; it < 8; it++) {
                int row = rr + it * 16;
                int grow = row0 + row;
                float4 v = make_float4(0.f, 0.f, 0.f, 0.f);
                if (grow < NN)
                    v = *(const float4*)(xsrc + (size_t)grow * HD + kofs + k4 * 4);
                ((float4*)(x_s + row * SBK))[k4] = v;
            }
        }
        // stage w: 64 k x 128 c from pre-transposed wT
        {
            int c4 = tid & 31, kk = tid >> 5;
#pragma unroll
            for (int it = 0; it < 8; it++) {
                int k = kk + it * 8;
                ((float4*)(w_s + k * HD))[c4] =
                    *(const float4*)(wT + (size_t)(ch * SBK + k) * HD + c4 * 4);
            }
        }
        __syncthreads();

#pragma unroll 4
        for (int k4i = 0; k4i < SBK / 4; k4i++) {
            float4 b0 = ((float4*)(w_s + (4 * k4i + 0) * HD))[tx];
            float4 b1 = ((float4*)(w_s + (4 * k4i + 1) * HD))[tx];
            float4 b2 = ((float4*)(w_s + (4 * k4i + 2) * HD))[tx];
            float4 b3 = ((float4*)(w_s + (4 * k4i + 3) * HD))[tx];
#pragma unroll
            for (int r = 0; r < 16; r++) {
                float4 a = ((float4*)(x_s + (wy * 16 + r) * SBK))[k4i];  // broadcast
                acc[r][0] += a.x * b0.x + a.y * b1.x + a.z * b2.x + a.w * b3.x;
                acc[r][1] += a.x * b0.y + a.y * b1.y + a.z * b2.y + a.w * b3.y;
                acc[r][2] += a.x * b0.z + a.y * b1.z + a.z * b2.z + a.w * b3.z;
                acc[r][3] += a.x * b0.w + a.y * b1.w + a.z * b2.w + a.w * b3.w;
            }
        }
        __syncthreads();
    }

    // epilogue: bias + LayerNorm (full reduction within warp) + ReLU
    float4 blv = *(const float4*)(bl + tx * 4);
    float4 gv  = *(const float4*)(gg + tx * 4);
    float4 bev = *(const float4*)(be + tx * 4);
#pragma unroll
    for (int r = 0; r < 16; r++) {
        float a0 = acc[r][0] + blv.x;
        float a1 = acc[r][1] + blv.y;
        float a2 = acc[r][2] + blv.z;
        float a3 = acc[r][3] + blv.w;
        float s1 = (a0 + a1) + (a2 + a3);
        float s2 = (a0 * a0 + a1 * a1) + (a2 * a2 + a3 * a3);
#pragma unroll
        for (int o = 16; o; o >>= 1) {
            s1 += __shfl_xor_sync(0xffffffffu, s1, o);
            s2 += __shfl_xor_sync(0xffffffffu, s2, o);
        }
        float mean = s1 * (1.0f / HD);
        float var  = s2 * (1.0f / HD) - mean * mean;
        float rs   = rsqrtf(var + LN_EPS);
        int row = row0 + wy * 16 + r;
        if (row < NN) {
            float4 o4;
            o4.x = fmaxf((a0 - mean) * rs * gv.x + bev.x, 0.f);
            o4.y = fmaxf((a1 - mean) * rs * gv.y + bev.y, 0.f);
            o4.z = fmaxf((a2 - mean) * rs * gv.z + bev.z, 0.f);
            o4.w = fmaxf((a3 - mean) * rs * gv.w + bev.w, 0.f);
            *(float4*)(hout + (size_t)row * HD + tx * 4) = o4;
        }
    }
}

// ---------------- pooling ----------------
#define POOL_CHUNK 256
__global__ void pool_kernel(const float* __restrict__ node,
                            const int* __restrict__ batch) {
    int n0 = blockIdx.x * POOL_CHUNK;
    int n1 = min(n0 + POOL_CHUNK, NN);
    int c = threadIdx.x;
    int cur = __ldg(&batch[n0]);
    float s = 0.0f, m = 0.0f;
    int cnt = 0;
    for (int i = n0; i < n1; i++) {
        int b = __ldg(&batch[i]);
        if (b != cur) {
            atomicAdd(&g_psum[cur * HD + c], s);
            atomicMax(&g_pmax[cur * HD + c], __float_as_uint(m));
            if (c == 0) atomicAdd(&g_pcnt[cur], cnt);
            cur = b; s = 0.0f; m = 0.0f; cnt = 0;
        }
        float v = node[(size_t)i * HD + c];
        s += v;
        m = fmaxf(m, v);
        cnt++;
    }
    atomicAdd(&g_psum[cur * HD + c], s);
    atomicMax(&g_pmax[cur * HD + c], __float_as_uint(m));
    if (c == 0) atomicAdd(&g_pcnt[cur], cnt);
}

__global__ void finalize_kernel(float* __restrict__ out) {
    int i = blockIdx.x * blockDim.x + threadIdx.x;
    if (i >= BB * HD) return;
    int b = i >> 7;
    int c = i & (HD - 1);
    float cnt = fmaxf((float)g_pcnt[b], 1.0f);
    out[(size_t)NN * HD + b * (2 * HD) + c] = g_psum[i] / cnt;
    out[(size_t)NN * HD + b * (2 * HD) + HD + c] = __uint_as_float(g_pmax[i]);
}

// ---------------- launch ----------------
extern "C" void kernel_launch(void* const* d_in, const int* in_sizes, int n_in,
                              void* d_out, int out_size) {
    const float* x   = (const float*)d_in[0];
    const int* eidx  = (const int*)d_in[1];
    const int* batch = (const int*)d_in[2];
    const float* W0 = (const float*)d_in[3];
    const float* b0 = (const float*)d_in[4];
    const float* g0 = (const float*)d_in[5];
    const float* be0 = (const float*)d_in[6];
    const float* Wl1 = (const float*)d_in[7];
    const float* bl1 = (const float*)d_in[8];
    const float* Wr1 = (const float*)d_in[9];
    const float* g1 = (const float*)d_in[10];
    const float* be1 = (const float*)d_in[11];
    const float* Wl2 = (const float*)d_in[12];
    const float* bl2 = (const float*)d_in[13];
    const float* Wr2 = (const float*)d_in[14];
    const float* g2 = (const float*)d_in[15];
    const float* be2 = (const float*)d_in[16];
    const float* Wl3 = (const float*)d_in[17];
    const float* bl3 = (const float*)d_in[18];
    const float* Wr3 = (const float*)d_in[19];
    const float* g3 = (const float*)d_in[20];
    const float* be3 = (const float*)d_in[21];
    float* out = (float*)d_out;

    const int* src = eidx;       // edge_index[0]
    const int* dst = eidx + EE;  // edge_index[1]

    static int attr_set = 0;
    if (!attr_set) {
        cudaFuncSetAttribute(sage2_kernel,
                             cudaFuncAttributeMaxDynamicSharedMemorySize, SAGE2_SMEM);
        attr_set = 1;
    }

    float* wT = 0;
    cudaGetSymbolAddress((void**)&wT, g_wT);

    // init + CSR build + weight transpose
    init_kernel<<<(NN + 255) / 256, 256>>>();
    wt_kernel<<<(3 * KK * HD + 255) / 256, 256>>>(Wl1, Wr1, Wl2, Wr2, Wl3, Wr3);
    deg_kernel<<<(EE + 255) / 256, 256>>>(dst);
    scan_kernel<<<1, 1024>>>();
    build_csr_kernel<<<(EE + 255) / 256, 256>>>(src, dst);

    // embed
    embed_kernel<<<NN / ROWS_E, HD>>>(x, W0, b0, g0, be0, g_h0);

    int agg_blocks = (NN * 32 + 255) / 256;
    int sage_blocks = (NN + 127) / 128;

    // layer 1: h0 -> h1
    aggregate_kernel<<<agg_blocks, 256>>>(g_h0);
    sage2_kernel<<<sage_blocks, 256, SAGE2_SMEM>>>(g_h0, wT + 0 * KK * HD, bl1, g1, be1, g_h1);
    // layer 2: h1 -> h0
    aggregate_kernel<<<agg_blocks, 256>>>(g_h1);
    sage2_kernel<<<sage_blocks, 256, SAGE2_SMEM>>>(g_h1, wT + 1 * KK * HD, bl2, g2, be2, g_h0);
    // layer 3: h0 -> out
    aggregate_kernel<<<agg_blocks, 256>>>(g_h0);
    sage2_kernel<<<sage_blocks, 256, SAGE2_SMEM>>>(g_h0, wT + 2 * KK * HD, bl3, g3, be3, out);

    // pooling
    pool_kernel<<<(NN + POOL_CHUNK - 1) / POOL_CHUNK, HD>>>(out, batch);
    finalize_kernel<<<(BB * HD + 255) / 256, 256>>>(out);
}